// round 11
// baseline (speedup 1.0000x reference)
#include <cuda_runtime.h>

// BaseTextureDiffusion: out[b,c,h,w] = sum_{k=0..48} weights[b,c,k,h,w] *
//                       latent_edgepadded[b,c, h+k/7-3, w+k%7-3]
// Shapes: latent (2,24,256,256) f32, weights (2,24,49,256,256) f32, R=7.
//
// HBM-bound on the 616MB read-once weights stream. R11 = R10 (90.2us:
// rows 0-1 prefilled under staging, row i+2 LDG burst before row i FMAs,
// occ-3, vectorized latent staging, __ldcs/__stcs) + ZERO-REGISTER L2
// PREFETCH running two rows ahead of the LDG window:
//   - rows 2,3 prefetched to L2 before the staging loop
//   - row i+4 prefetched inside iteration i
// LDG bursts then hit L2 (~250cyc) instead of DRAM (~1000cyc), doubling
// effective pipeline depth with no register cost.

#define BB 2
#define CC 24
#define HH 256
#define WW 256
#define RR 7
#define PAD 3
#define HW (HH * WW)

#define TILE_ROWS 4                   // output rows per block
#define SROWS (TILE_ROWS + 2 * PAD)   // 10
#define SCOLS 264                     // latent cols -4..259
#define SC4   (SCOLS / 4)             // 66 float4 slots per tile row

__device__ __forceinline__ void l2_prefetch(const void* p) {
    asm volatile("prefetch.global.L2 [%0];" :: "l"(p));
}

__global__ __launch_bounds__(256, 3)
void texdiff_kernel(const float* __restrict__ latent,
                    const float* __restrict__ weights,
                    float* __restrict__ out)
{
    __shared__ float tile[SROWS][SCOLS];

    const int bc = blockIdx.z;                 // 0..47  (b*C + c)
    const int h0 = blockIdx.y * TILE_ROWS;     // first output row of tile
    const int x  = threadIdx.x;                // 0..63 : float4 lane over w
    const int y  = threadIdx.y;                // 0..3  : row within tile
    const int tid = y * 64 + x;                // 0..255
    const int w0  = 4 * x;

    const int h = h0 + y;
    const float* wbase = weights + (long)bc * (RR * RR) * HW + h * WW + w0;

    // Prefetch window rows 0 and 1 into registers before staging — latency
    // hidden under the latent tile staging below.
    float4 wv[2][RR];
    #pragma unroll
    for (int j = 0; j < RR; j++)
        wv[0][j] = __ldcs((const float4*)(wbase + (long)j * HW));
    #pragma unroll
    for (int j = 0; j < RR; j++)
        wv[1][j] = __ldcs((const float4*)(wbase + (long)(RR + j) * HW));

    // L2-prefetch rows 2 and 3 (two rows ahead of the LDG window).
    #pragma unroll
    for (int j = 0; j < RR; j++)
        l2_prefetch(wbase + (long)(2 * RR + j) * HW);
    #pragma unroll
    for (int j = 0; j < RR; j++)
        l2_prefetch(wbase + (long)(3 * RR + j) * HW);

    const float* lat = latent + (long)bc * HW;

    // Stage latent tile with edge clamp, vectorized:
    // interior slots are aligned float4 copies; apron slots are clamped
    // scalar splats of column 0 / 255.
    #pragma unroll
    for (int idx = tid; idx < SROWS * SC4; idx += 256) {
        int r  = idx / SC4;
        int c4 = idx - r * SC4;
        int gh = h0 + r - PAD;
        gh = gh < 0 ? 0 : (gh > HH - 1 ? HH - 1 : gh);
        const float* lrow = lat + gh * WW;
        float4* dst = (float4*)&tile[r][c4 * 4];
        if (c4 == 0) {
            float v = lrow[0];
            *dst = make_float4(v, v, v, v);
        } else if (c4 == SC4 - 1) {
            float v = lrow[WW - 1];
            *dst = make_float4(v, v, v, v);
        } else {
            *dst = *(const float4*)(lrow + (c4 - 1) * 4);
        }
    }
    __syncthreads();

    float4 acc = make_float4(0.f, 0.f, 0.f, 0.f);

    // wv[i&1] holds row i; row i+1 resident; rows i+2,i+3 inbound in L2.
    #pragma unroll
    for (int i = 0; i < RR; i++) {
        const int cur = i & 1;

        // Snapshot row i's weights so the buffer slot can be reloaded now.
        float4 wr[RR];
        #pragma unroll
        for (int j = 0; j < RR; j++)
            wr[j] = wv[cur][j];

        // Issue row i+2's LDG burst BEFORE the FMAs (loads lead consumes).
        if (i < RR - 2) {
            #pragma unroll
            for (int j = 0; j < RR; j++)
                wv[cur][j] =
                    __ldcs((const float4*)(wbase + (long)((i + 2) * RR + j) * HW));
        }

        // L2-prefetch row i+4 (keeps prefetch horizon 2 rows past LDG).
        if (i < RR - 4) {
            #pragma unroll
            for (int j = 0; j < RR; j++)
                l2_prefetch(wbase + (long)((i + 4) * RR + j) * HW);
        }

        // 12 consecutive latent values covering cols w0-3 .. w0+8
        const float4* srow = (const float4*)&tile[y + i][w0];
        float4 a = srow[0];
        float4 b = srow[1];
        float4 c = srow[2];
        float r[12] = { a.x, a.y, a.z, a.w,
                        b.x, b.y, b.z, b.w,
                        c.x, c.y, c.z, c.w };

        #pragma unroll
        for (int j = 0; j < RR; j++) {
            acc.x += wr[j].x * r[1 + j];
            acc.y += wr[j].y * r[2 + j];
            acc.z += wr[j].z * r[3 + j];
            acc.w += wr[j].w * r[4 + j];
        }
    }

    __stcs((float4*)(out + (long)bc * HW + h * WW + w0), acc);
}

extern "C" void kernel_launch(void* const* d_in, const int* in_sizes, int n_in,
                              void* d_out, int out_size)
{
    const float* latent  = (const float*)d_in[0];
    const float* weights = (const float*)d_in[1];
    // d_in[2] = window_size (int scalar, always 7 here)
    float* out = (float*)d_out;

    dim3 block(64, TILE_ROWS, 1);
    dim3 grid(1, HH / TILE_ROWS, BB * CC);
    texdiff_kernel<<<grid, block>>>(latent, weights, out);
}

// round 12
// speedup vs baseline: 1.0534x; 1.0534x over previous
#include <cuda_runtime.h>

// BaseTextureDiffusion: out[b,c,h,w] = sum_{k=0..48} weights[b,c,k,h,w] *
//                       latent_edgepadded[b,c, h+k/7-3, w+k%7-3]
// Shapes: latent (2,24,256,256) f32, weights (2,24,49,256,256) f32, R=7.
//
// FINAL (R12 = exact revert to R10, best @ 90.2us, 7.12 TB/s = 89% of HBM
// spec). HBM-bound on the 616MB read-once weights stream. Schedule:
//  - window rows 0 AND 1 prefetched into registers before latent staging
//    (their DRAM latency rides under the staging loads),
//  - steady state: row i+2's batched 7x LDG.128 burst issues BEFORE row
//    i's FMAs (loads always lead consumes, distance-2),
//  - 4-row tiles, 3072 blocks, occ-3 (80 regs), vectorized latent staging
//    into a 10x264 smem tile, __ldcs weights / __stcs out.
// Ruled out by measurement: 8-row tiles (R4), persistent grid (R3),
// rotating buffer @ occ-4 (R8), L2 prefetch (R11) — all regressed.

#define BB 2
#define CC 24
#define HH 256
#define WW 256
#define RR 7
#define PAD 3
#define HW (HH * WW)

#define TILE_ROWS 4                   // output rows per block
#define SROWS (TILE_ROWS + 2 * PAD)   // 10
#define SCOLS 264                     // latent cols -4..259
#define SC4   (SCOLS / 4)             // 66 float4 slots per tile row

__global__ __launch_bounds__(256, 3)
void texdiff_kernel(const float* __restrict__ latent,
                    const float* __restrict__ weights,
                    float* __restrict__ out)
{
    __shared__ float tile[SROWS][SCOLS];

    const int bc = blockIdx.z;                 // 0..47  (b*C + c)
    const int h0 = blockIdx.y * TILE_ROWS;     // first output row of tile
    const int x  = threadIdx.x;                // 0..63 : float4 lane over w
    const int y  = threadIdx.y;                // 0..3  : row within tile
    const int tid = y * 64 + x;                // 0..255
    const int w0  = 4 * x;

    const int h = h0 + y;
    const float* wbase = weights + (long)bc * (RR * RR) * HW + h * WW + w0;

    // Prefetch window rows 0 and 1 before staging — latency hidden under
    // the latent tile staging below.
    float4 wv[2][RR];
    #pragma unroll
    for (int j = 0; j < RR; j++)
        wv[0][j] = __ldcs((const float4*)(wbase + (long)j * HW));
    #pragma unroll
    for (int j = 0; j < RR; j++)
        wv[1][j] = __ldcs((const float4*)(wbase + (long)(RR + j) * HW));

    const float* lat = latent + (long)bc * HW;

    // Stage latent tile with edge clamp, vectorized:
    // interior slots are aligned float4 copies; apron slots are clamped
    // scalar splats of column 0 / 255.
    #pragma unroll
    for (int idx = tid; idx < SROWS * SC4; idx += 256) {
        int r  = idx / SC4;
        int c4 = idx - r * SC4;
        int gh = h0 + r - PAD;
        gh = gh < 0 ? 0 : (gh > HH - 1 ? HH - 1 : gh);
        const float* lrow = lat + gh * WW;
        float4* dst = (float4*)&tile[r][c4 * 4];
        if (c4 == 0) {
            float v = lrow[0];
            *dst = make_float4(v, v, v, v);
        } else if (c4 == SC4 - 1) {
            float v = lrow[WW - 1];
            *dst = make_float4(v, v, v, v);
        } else {
            *dst = *(const float4*)(lrow + (c4 - 1) * 4);
        }
    }
    __syncthreads();

    float4 acc = make_float4(0.f, 0.f, 0.f, 0.f);

    // wv[i&1] holds row i; row i+1 already in flight / resident.
    // Each iteration: stash row i's values, issue row i+2's burst into the
    // just-freed buffer slot, then FMA row i.
    #pragma unroll
    for (int i = 0; i < RR; i++) {
        const int cur = i & 1;

        // Snapshot row i's weights so the buffer slot can be reloaded now.
        float4 wr[RR];
        #pragma unroll
        for (int j = 0; j < RR; j++)
            wr[j] = wv[cur][j];

        // Issue row i+2's burst BEFORE the FMAs (loads lead consumes).
        if (i < RR - 2) {
            #pragma unroll
            for (int j = 0; j < RR; j++)
                wv[cur][j] =
                    __ldcs((const float4*)(wbase + (long)((i + 2) * RR + j) * HW));
        }

        // 12 consecutive latent values covering cols w0-3 .. w0+8
        const float4* srow = (const float4*)&tile[y + i][w0];
        float4 a = srow[0];
        float4 b = srow[1];
        float4 c = srow[2];
        float r[12] = { a.x, a.y, a.z, a.w,
                        b.x, b.y, b.z, b.w,
                        c.x, c.y, c.z, c.w };

        #pragma unroll
        for (int j = 0; j < RR; j++) {
            acc.x += wr[j].x * r[1 + j];
            acc.y += wr[j].y * r[2 + j];
            acc.z += wr[j].z * r[3 + j];
            acc.w += wr[j].w * r[4 + j];
        }
    }

    __stcs((float4*)(out + (long)bc * HW + h * WW + w0), acc);
}

extern "C" void kernel_launch(void* const* d_in, const int* in_sizes, int n_in,
                              void* d_out, int out_size)
{
    const float* latent  = (const float*)d_in[0];
    const float* weights = (const float*)d_in[1];
    // d_in[2] = window_size (int scalar, always 7 here)
    float* out = (float*)d_out;

    dim3 block(64, TILE_ROWS, 1);
    dim3 grid(1, HH / TILE_ROWS, BB * CC);
    texdiff_kernel<<<grid, block>>>(latent, weights, out);
}

// round 13
// speedup vs baseline: 1.0691x; 1.0148x over previous
#include <cuda_runtime.h>

// BaseTextureDiffusion: out[b,c,h,w] = sum_{k=0..48} weights[b,c,k,h,w] *
//                       latent_edgepadded[b,c, h+k/7-3, w+k%7-3]
// Shapes: latent (2,24,256,256) f32, weights (2,24,49,256,256) f32, R=7.
//
// FINAL converged kernel (R10 schedule; best measured 90.2us, noise band
// +/-2-4us; 7.1 TB/s effective = ~89% of HBM spec). HBM-bound on the 616MB
// read-once weights stream. Schedule:
//  - window rows 0 AND 1 prefetched into registers before latent staging
//    (their DRAM latency rides under the staging loads),
//  - steady state: row i+2's batched 7x LDG.128 burst issues BEFORE row
//    i's FMAs (loads always lead consumes, distance-2),
//  - 4-row tiles, 3072 blocks, occ-3 (80 regs), vectorized latent staging
//    into a 10x264 smem tile, __ldcs weights / __stcs out.
// R13 micro-trim: int32 offsets (all indices < 2^31) to shorten address
// IMAD chains. Ruled out by measurement: 8-row tiles (R4), persistent
// grid (R3), rotating buffer @ occ-4 (R8), L2 prefetch (R11).

#define BB 2
#define CC 24
#define HH 256
#define WW 256
#define RR 7
#define PAD 3
#define HW (HH * WW)

#define TILE_ROWS 4                   // output rows per block
#define SROWS (TILE_ROWS + 2 * PAD)   // 10
#define SCOLS 264                     // latent cols -4..259
#define SC4   (SCOLS / 4)             // 66 float4 slots per tile row

__global__ __launch_bounds__(256, 3)
void texdiff_kernel(const float* __restrict__ latent,
                    const float* __restrict__ weights,
                    float* __restrict__ out)
{
    __shared__ float tile[SROWS][SCOLS];

    const int bc = blockIdx.z;                 // 0..47  (b*C + c)
    const int h0 = blockIdx.y * TILE_ROWS;     // first output row of tile
    const int x  = threadIdx.x;                // 0..63 : float4 lane over w
    const int y  = threadIdx.y;                // 0..3  : row within tile
    const int tid = y * 64 + x;                // 0..255
    const int w0  = 4 * x;

    const int h = h0 + y;
    // All weight indices fit in int32 (max ~154M elements).
    const float* wbase = weights + bc * (RR * RR * HW) + h * WW + w0;

    // Prefetch window rows 0 and 1 before staging — latency hidden under
    // the latent tile staging below.
    float4 wv[2][RR];
    #pragma unroll
    for (int j = 0; j < RR; j++)
        wv[0][j] = __ldcs((const float4*)(wbase + j * HW));
    #pragma unroll
    for (int j = 0; j < RR; j++)
        wv[1][j] = __ldcs((const float4*)(wbase + (RR + j) * HW));

    const float* lat = latent + bc * HW;

    // Stage latent tile with edge clamp, vectorized:
    // interior slots are aligned float4 copies; apron slots are clamped
    // scalar splats of column 0 / 255.
    #pragma unroll
    for (int idx = tid; idx < SROWS * SC4; idx += 256) {
        int r  = idx / SC4;
        int c4 = idx - r * SC4;
        int gh = h0 + r - PAD;
        gh = gh < 0 ? 0 : (gh > HH - 1 ? HH - 1 : gh);
        const float* lrow = lat + gh * WW;
        float4* dst = (float4*)&tile[r][c4 * 4];
        if (c4 == 0) {
            float v = lrow[0];
            *dst = make_float4(v, v, v, v);
        } else if (c4 == SC4 - 1) {
            float v = lrow[WW - 1];
            *dst = make_float4(v, v, v, v);
        } else {
            *dst = *(const float4*)(lrow + (c4 - 1) * 4);
        }
    }
    __syncthreads();

    float4 acc = make_float4(0.f, 0.f, 0.f, 0.f);

    // wv[i&1] holds row i; row i+1 already in flight / resident.
    // Each iteration: stash row i's values, issue row i+2's burst into the
    // just-freed buffer slot, then FMA row i.
    #pragma unroll
    for (int i = 0; i < RR; i++) {
        const int cur = i & 1;

        // Snapshot row i's weights so the buffer slot can be reloaded now.
        float4 wr[RR];
        #pragma unroll
        for (int j = 0; j < RR; j++)
            wr[j] = wv[cur][j];

        // Issue row i+2's burst BEFORE the FMAs (loads lead consumes).
        if (i < RR - 2) {
            #pragma unroll
            for (int j = 0; j < RR; j++)
                wv[cur][j] = __ldcs((const float4*)(wbase + ((i + 2) * RR + j) * HW));
        }

        // 12 consecutive latent values covering cols w0-3 .. w0+8
        const float4* srow = (const float4*)&tile[y + i][w0];
        float4 a = srow[0];
        float4 b = srow[1];
        float4 c = srow[2];
        float r[12] = { a.x, a.y, a.z, a.w,
                        b.x, b.y, b.z, b.w,
                        c.x, c.y, c.z, c.w };

        #pragma unroll
        for (int j = 0; j < RR; j++) {
            acc.x += wr[j].x * r[1 + j];
            acc.y += wr[j].y * r[2 + j];
            acc.z += wr[j].z * r[3 + j];
            acc.w += wr[j].w * r[4 + j];
        }
    }

    __stcs((float4*)(out + bc * HW + h * WW + w0), acc);
}

extern "C" void kernel_launch(void* const* d_in, const int* in_sizes, int n_in,
                              void* d_out, int out_size)
{
    const float* latent  = (const float*)d_in[0];
    const float* weights = (const float*)d_in[1];
    // d_in[2] = window_size (int scalar, always 7 here)
    float* out = (float*)d_out;

    dim3 block(64, TILE_ROWS, 1);
    dim3 grid(1, HH / TILE_ROWS, BB * CC);
    texdiff_kernel<<<grid, block>>>(latent, weights, out);
}

// round 14
// speedup vs baseline: 1.0963x; 1.0255x over previous
#include <cuda_runtime.h>

// BaseTextureDiffusion: out[b,c,h,w] = sum_{k=0..48} weights[b,c,k,h,w] *
//                       latent_edgepadded[b,c, h+k/7-3, w+k%7-3]
// Shapes: latent (2,24,256,256) f32, weights (2,24,49,256,256) f32, R=7.
//
// FINAL converged kernel. Best wall-clock 90.2us (noise band +/-2-4us);
// best profiled steady state: DRAM 85.8%, 6794 GB/s (~7.1 TB/s wall-clock
// effective = ~89% of HBM spec). HBM-bound on the 616MB read-once weights
// stream; at 24:1 read:write this is the practical ceiling.
// Schedule (each piece measured):
//  - window rows 0 AND 1 prefetched into registers before latent staging
//    (their DRAM latency rides under the staging loads),
//  - steady state: row i+2's batched 7x LDG.128 burst issues BEFORE row
//    i's FMAs (loads always lead consumes, distance-2),
//  - 4-row tiles, 3072 blocks, occ-3 (80 regs), vectorized latent staging
//    into a 10x264 smem tile, __ldcs weights / __stcs out, int32 offsets.
// Ruled out by measurement: 8-row tiles (R4), persistent grid (R3),
// rotating buffer @ occ-4 (R8), L2 prefetch (R11), interleaved reloads (R8).

#define BB 2
#define CC 24
#define HH 256
#define WW 256
#define RR 7
#define PAD 3
#define HW (HH * WW)

#define TILE_ROWS 4                   // output rows per block
#define SROWS (TILE_ROWS + 2 * PAD)   // 10
#define SCOLS 264                     // latent cols -4..259
#define SC4   (SCOLS / 4)             // 66 float4 slots per tile row

__global__ __launch_bounds__(256, 3)
void texdiff_kernel(const float* __restrict__ latent,
                    const float* __restrict__ weights,
                    float* __restrict__ out)
{
    __shared__ float tile[SROWS][SCOLS];

    const int bc = blockIdx.z;                 // 0..47  (b*C + c)
    const int h0 = blockIdx.y * TILE_ROWS;     // first output row of tile
    const int x  = threadIdx.x;                // 0..63 : float4 lane over w
    const int y  = threadIdx.y;                // 0..3  : row within tile
    const int tid = y * 64 + x;                // 0..255
    const int w0  = 4 * x;

    const int h = h0 + y;
    // All weight indices fit in int32 (max ~154M elements).
    const float* wbase = weights + bc * (RR * RR * HW) + h * WW + w0;

    // Prefetch window rows 0 and 1 before staging — latency hidden under
    // the latent tile staging below.
    float4 wv[2][RR];
    #pragma unroll
    for (int j = 0; j < RR; j++)
        wv[0][j] = __ldcs((const float4*)(wbase + j * HW));
    #pragma unroll
    for (int j = 0; j < RR; j++)
        wv[1][j] = __ldcs((const float4*)(wbase + (RR + j) * HW));

    const float* lat = latent + bc * HW;

    // Stage latent tile with edge clamp, vectorized:
    // interior slots are aligned float4 copies; apron slots are clamped
    // scalar splats of column 0 / 255.
    #pragma unroll
    for (int idx = tid; idx < SROWS * SC4; idx += 256) {
        int r  = idx / SC4;
        int c4 = idx - r * SC4;
        int gh = h0 + r - PAD;
        gh = gh < 0 ? 0 : (gh > HH - 1 ? HH - 1 : gh);
        const float* lrow = lat + gh * WW;
        float4* dst = (float4*)&tile[r][c4 * 4];
        if (c4 == 0) {
            float v = lrow[0];
            *dst = make_float4(v, v, v, v);
        } else if (c4 == SC4 - 1) {
            float v = lrow[WW - 1];
            *dst = make_float4(v, v, v, v);
        } else {
            *dst = *(const float4*)(lrow + (c4 - 1) * 4);
        }
    }
    __syncthreads();

    float4 acc = make_float4(0.f, 0.f, 0.f, 0.f);

    // wv[i&1] holds row i; row i+1 already in flight / resident.
    // Each iteration: stash row i's values, issue row i+2's burst into the
    // just-freed buffer slot, then FMA row i.
    #pragma unroll
    for (int i = 0; i < RR; i++) {
        const int cur = i & 1;

        // Snapshot row i's weights so the buffer slot can be reloaded now.
        float4 wr[RR];
        #pragma unroll
        for (int j = 0; j < RR; j++)
            wr[j] = wv[cur][j];

        // Issue row i+2's burst BEFORE the FMAs (loads lead consumes).
        if (i < RR - 2) {
            #pragma unroll
            for (int j = 0; j < RR; j++)
                wv[cur][j] = __ldcs((const float4*)(wbase + ((i + 2) * RR + j) * HW));
        }

        // 12 consecutive latent values covering cols w0-3 .. w0+8
        const float4* srow = (const float4*)&tile[y + i][w0];
        float4 a = srow[0];
        float4 b = srow[1];
        float4 c = srow[2];
        float r[12] = { a.x, a.y, a.z, a.w,
                        b.x, b.y, b.z, b.w,
                        c.x, c.y, c.z, c.w };

        #pragma unroll
        for (int j = 0; j < RR; j++) {
            acc.x += wr[j].x * r[1 + j];
            acc.y += wr[j].y * r[2 + j];
            acc.z += wr[j].z * r[3 + j];
            acc.w += wr[j].w * r[4 + j];
        }
    }

    __stcs((float4*)(out + bc * HW + h * WW + w0), acc);
}

extern "C" void kernel_launch(void* const* d_in, const int* in_sizes, int n_in,
                              void* d_out, int out_size)
{
    const float* latent  = (const float*)d_in[0];
    const float* weights = (const float*)d_in[1];
    // d_in[2] = window_size (int scalar, always 7 here)
    float* out = (float*)d_out;

    dim3 block(64, TILE_ROWS, 1);
    dim3 grid(1, HH / TILE_ROWS, BB * CC);
    texdiff_kernel<<<grid, block>>>(latent, weights, out);
}